// round 6
// baseline (speedup 1.0000x reference)
#include <cuda_runtime.h>
#include <math.h>

#define TT 2048
#define HH 1024
#define II 1024
#define NE 16
#define KTOP 4
#define EPSF 1e-5f
#define ALPHAF 1.702f
#define LIMITF 7.0f

#define BM 128
#define BN 128
#define BK 16
#define PAD 20                       // 16+4 words/row -> conflict-free LDSM
#define NSTG 3
#define STG_WORDS (128 * PAD)        // words per stage per operand
#define SMEM_BYTES (NSTG * STG_WORDS * 4 * 2)

// ---------------- scratch (static device globals; no allocation) -------------
__device__ __align__(16) float g_t[TT * HH];            // tf32-rounded rmsnorm out
__device__ __align__(16) float g_s[TT * KTOP * II];     // tf32-rounded swiglu out
__device__ __align__(16) float g_y[TT * KTOP * HH];
__device__ float g_slot_w[TT * KTOP];
__device__ int   g_expert_cnt[NE];
__device__ int   g_expert_slots[NE * TT];

// ---------------- helpers ------------------------------------------------------
__device__ __forceinline__ unsigned f2tf(float f) {
    unsigned r;
    asm("cvt.rna.tf32.f32 %0, %1;" : "=r"(r) : "f"(f));
    return r;
}

__device__ __forceinline__ void mma_tf32(float* d, const unsigned* a, const unsigned* b) {
    asm volatile(
        "mma.sync.aligned.m16n8k8.row.col.f32.tf32.tf32.f32 "
        "{%0,%1,%2,%3}, {%4,%5,%6,%7}, {%8,%9}, {%0,%1,%2,%3};"
        : "+f"(d[0]), "+f"(d[1]), "+f"(d[2]), "+f"(d[3])
        : "r"(a[0]), "r"(a[1]), "r"(a[2]), "r"(a[3]), "r"(b[0]), "r"(b[1]));
}

__device__ __forceinline__ void ldsm4(unsigned* r, unsigned addr) {
    asm volatile("ldmatrix.sync.aligned.m8n8.x4.shared.b16 {%0,%1,%2,%3}, [%4];"
        : "=r"(r[0]), "=r"(r[1]), "=r"(r[2]), "=r"(r[3]) : "r"(addr));
}

__device__ __forceinline__ void cp16(unsigned dst, const void* src) {
    asm volatile("cp.async.cg.shared.global [%0], [%1], 16;" :: "r"(dst), "l"(src));
}
#define CP_COMMIT() asm volatile("cp.async.commit_group;")
#define CP_WAIT1()  asm volatile("cp.async.wait_group 1;")

// ---------------- kernel 0 -----------------------------------------------------
__global__ void zero_cnt_kernel() {
    if (threadIdx.x < NE) g_expert_cnt[threadIdx.x] = 0;
}

// ---------------- kernel 1: fused RMSNorm + gate + top4 + routing -------------
// 256 threads, one token per block. Gate logits computed from UNROUNDED t;
// g_t written tf32-RNA rounded for direct cp.async staging in mlp1.
__global__ void norm_gate_kernel(const float* __restrict__ x,
                                 const float* __restrict__ scale,
                                 const float* __restrict__ gate_w,
                                 const float* __restrict__ gate_b) {
    int t = blockIdx.x;
    int tid = threadIdx.x;
    __shared__ float ts[HH];
    __shared__ float gv[NE];
    __shared__ float red[8];

    float4 v = *((const float4*)(x + (size_t)t * HH) + tid);
    float ss = v.x * v.x + v.y * v.y + v.z * v.z + v.w * v.w;
    #pragma unroll
    for (int o = 16; o; o >>= 1) ss += __shfl_xor_sync(0xffffffffu, ss, o);
    if ((tid & 31) == 0) red[tid >> 5] = ss;
    __syncthreads();
    if (tid < 8) {
        float s2 = red[tid];
        #pragma unroll
        for (int o = 4; o; o >>= 1) s2 += __shfl_xor_sync(0xffu, s2, o);
        if (tid == 0) red[0] = s2;
    }
    __syncthreads();
    float rms = rsqrtf(red[0] * (1.0f / HH) + EPSF);
    float4 sc = *((const float4*)scale + tid);
    float4 tv;
    tv.x = v.x * rms * sc.x; tv.y = v.y * rms * sc.y;
    tv.z = v.z * rms * sc.z; tv.w = v.w * rms * sc.w;
    *((float4*)ts + tid) = tv;
    // rounded copy for the GEMM
    uint4 u;
    u.x = f2tf(tv.x); u.y = f2tf(tv.y); u.z = f2tf(tv.z); u.w = f2tf(tv.w);
    *((uint4*)(g_t + (size_t)t * HH) + tid) = u;
    __syncthreads();

    int g = tid >> 4;
    int j = tid & 15;
    const float* wr = gate_w + g * HH;
    float sum = 0.f;
    for (int h = j; h < HH; h += 16) sum += ts[h] * wr[h];
    #pragma unroll
    for (int o = 8; o; o >>= 1) sum += __shfl_xor_sync(0xffffffffu, sum, o);
    if (j == 0) gv[g] = sum + gate_b[g];
    __syncthreads();

    if (tid == 0) {
        float vals[KTOP];
        int   idx[KTOP];
        bool  used[NE];
        #pragma unroll
        for (int e = 0; e < NE; e++) used[e] = false;
        #pragma unroll
        for (int k = 0; k < KTOP; k++) {
            float best = -INFINITY; int bi = 0;
            for (int e = 0; e < NE; e++)
                if (!used[e] && gv[e] > best) { best = gv[e]; bi = e; }
            used[bi] = true; vals[k] = best; idx[k] = bi;
        }
        float m = vals[0];
        float se = 0.f, w[KTOP];
        #pragma unroll
        for (int k = 0; k < KTOP; k++) { w[k] = __expf(vals[k] - m); se += w[k]; }
        float inv = 1.0f / se;
        #pragma unroll
        for (int k = 0; k < KTOP; k++) {
            int slot = t * KTOP + k;
            g_slot_w[slot] = w[k] * inv;
            int pos = atomicAdd(&g_expert_cnt[idx[k]], 1);
            g_expert_slots[idx[k] * TT + pos] = slot;
        }
    }
}

// ================= tf32 GEMMs ====================================================
// 128x128 block, 4 warps (64x64 warp tile), ldmatrix frags.
// A staged by 3-stage cp.async (source pre-rounded); B staged LDG->cvt->STS with
// one-iteration lookahead.

// ---------------- kernel 3: GEMM1 (even w1 rows) + bias + swiglu --------------
__global__ void __launch_bounds__(128, 2) mlp1_kernel(const float* __restrict__ w1,
                                                      const float* __restrict__ b1) {
    int e = blockIdx.z;
    int cnt = g_expert_cnt[e];
    int mt = blockIdx.y;
    if (mt * BM >= cnt) return;
    int ntB = blockIdx.x * BN;

    extern __shared__ __align__(16) unsigned smem[];
    unsigned* As = smem;                       // [NSTG][128][PAD]
    unsigned* Bs = smem + NSTG * STG_WORDS;    // [NSTG][128][PAD]
    __shared__ int slots[BM];

    int tid = threadIdx.x;
    {
        int idx = mt * BM + tid;
        slots[tid] = (idx < cnt) ? g_expert_slots[e * TT + idx] : -1;
    }
    __syncthreads();

    int lane = tid & 31, wid = tid >> 5;
    int wm = wid & 1, wn = wid >> 1;
    int grp = lane >> 2, tig = lane & 3;
    int rA = (lane & 7) + (((lane >> 3) & 1) << 3);
    int kA = (lane >> 4) << 2;
    int rB = (lane & 7) + ((lane >> 4) << 3);
    int kB = ((lane >> 3) & 1) << 2;
    unsigned aAddr = (unsigned)__cvta_generic_to_shared(&As[(wm * 64 + rA) * PAD + kA]);
    unsigned bAddr = (unsigned)__cvta_generic_to_shared(&Bs[(wn * 64 + rB) * PAD + kB]);

    int sr = tid >> 2;
    int kq = (tid & 3) * 4;
    const float* w1e = w1 + (size_t)e * (2 * II) * HH;
    const float* aptr[4];
    const float* bptr[4];
    unsigned aDst[4];
    #pragma unroll
    for (int i = 0; i < 4; i++) {
        int row = sr + i * 32;
        int s = slots[row];
        aptr[i] = g_t + (size_t)((s >= 0) ? (s >> 2) : 0) * HH + kq;
        bptr[i] = w1e + (size_t)(2 * (ntB + row)) * HH + kq;
        aDst[i] = (unsigned)__cvta_generic_to_shared(&As[row * PAD + kq]);
    }

    float acc[4][8][4] = {};
    float4 bv[4];

    // prologue: B stage0 LDG+cvt+STS; A stage0/1 cp.async; B stage1 LDG
    #pragma unroll
    for (int i = 0; i < 4; i++) {
        float4 b0 = *(const float4*)(bptr[i]);
        uint4 u;
        u.x = f2tf(b0.x); u.y = f2tf(b0.y); u.z = f2tf(b0.z); u.w = f2tf(b0.w);
        *(uint4*)&Bs[(sr + i * 32) * PAD + kq] = u;
    }
    #pragma unroll
    for (int i = 0; i < 4; i++) cp16(aDst[i], aptr[i]);
    CP_COMMIT();
    #pragma unroll
    for (int i = 0; i < 4; i++) cp16(aDst[i] + STG_WORDS * 4, aptr[i] + BK);
    CP_COMMIT();
    #pragma unroll
    for (int i = 0; i < 4; i++) bv[i] = *(const float4*)(bptr[i] + BK);

    const int NKT = HH / BK;
    for (int kb = 0; kb < NKT; kb++) {
        int cur = kb % NSTG;
        CP_WAIT1();
        __syncthreads();
        if (kb + 1 < NKT) {                      // STS B stage kb+1
            int st = (kb + 1) % NSTG;
            #pragma unroll
            for (int i = 0; i < 4; i++) {
                uint4 u;
                u.x = f2tf(bv[i].x); u.y = f2tf(bv[i].y);
                u.z = f2tf(bv[i].z); u.w = f2tf(bv[i].w);
                *(uint4*)&Bs[st * STG_WORDS + (sr + i * 32) * PAD + kq] = u;
            }
        }
        if (kb + 2 < NKT) {                      // A cp.async stage kb+2
            int st = (kb + 2) % NSTG;
            int ko = (kb + 2) * BK;
            #pragma unroll
            for (int i = 0; i < 4; i++)
                cp16(aDst[i] + (unsigned)(st * STG_WORDS * 4), aptr[i] + ko);
        }
        CP_COMMIT();
        if (kb + 2 < NKT) {                      // B LDG stage kb+2
            int ko = (kb + 2) * BK;
            #pragma unroll
            for (int i = 0; i < 4; i++) bv[i] = *(const float4*)(bptr[i] + ko);
        }
        unsigned aOff = aAddr + (unsigned)(cur * STG_WORDS * 4);
        unsigned bOff = bAddr + (unsigned)(cur * STG_WORDS * 4);
        #pragma unroll
        for (int ks = 0; ks < 2; ks++) {
            unsigned afr[4][4], bfr[4][4];
            #pragma unroll
            for (int sm = 0; sm < 4; sm++)
                ldsm4(afr[sm], aOff + (unsigned)((sm * 16 * PAD + ks * 8) * 4));
            #pragma unroll
            for (int p = 0; p < 4; p++)
                ldsm4(bfr[p], bOff + (unsigned)((p * 16 * PAD + ks * 8) * 4));
            #pragma unroll
            for (int sm = 0; sm < 4; sm++)
                #pragma unroll
                for (int sn = 0; sn < 8; sn++)
                    mma_tf32(acc[sm][sn], afr[sm], &bfr[sn >> 1][(sn & 1) * 2]);
        }
    }

    const float* b1e = b1 + e * (2 * II);
    #pragma unroll
    for (int sm = 0; sm < 4; sm++) {
        int rbase = wm * 64 + sm * 16 + grp;
        #pragma unroll
        for (int half = 0; half < 2; half++) {
            int row = rbase + half * 8;
            int slot = slots[row];
            if (slot < 0) continue;
            float* srow = g_s + (size_t)slot * II;
            #pragma unroll
            for (int sn = 0; sn < 8; sn++) {
                int n = ntB + wn * 64 + sn * 8 + 2 * tig;
                #pragma unroll
                for (int cc = 0; cc < 2; cc++) {
                    float hsum = acc[sm][sn][half * 2 + cc] + b1e[2 * (n + cc)];
                    float gl = fminf(hsum, LIMITF);
                    float sig = 1.0f / (1.0f + __expf(-ALPHAF * gl));
                    // store tf32-rounded so mlp2 can cp.async it directly
                    srow[n + cc] = __uint_as_float(f2tf(gl * sig * (LIMITF + 1.0f)));
                }
            }
        }
    }
}

// ---------------- kernel 4: GEMM2 + bias, scaled by routing weight ------------
__global__ void __launch_bounds__(128, 2) mlp2_kernel(const float* __restrict__ w2,
                                                      const float* __restrict__ b2) {
    int e = blockIdx.z;
    int cnt = g_expert_cnt[e];
    int mt = blockIdx.y;
    if (mt * BM >= cnt) return;
    int ntB = blockIdx.x * BN;

    extern __shared__ __align__(16) unsigned smem[];
    unsigned* As = smem;
    unsigned* Bs = smem + NSTG * STG_WORDS;
    __shared__ int slots[BM];

    int tid = threadIdx.x;
    {
        int idx = mt * BM + tid;
        slots[tid] = (idx < cnt) ? g_expert_slots[e * TT + idx] : -1;
    }
    __syncthreads();

    int lane = tid & 31, wid = tid >> 5;
    int wm = wid & 1, wn = wid >> 1;
    int grp = lane >> 2, tig = lane & 3;
    int rA = (lane & 7) + (((lane >> 3) & 1) << 3);
    int kA = (lane >> 4) << 2;
    int rB = (lane & 7) + ((lane >> 4) << 3);
    int kB = ((lane >> 3) & 1) << 2;
    unsigned aAddr = (unsigned)__cvta_generic_to_shared(&As[(wm * 64 + rA) * PAD + kA]);
    unsigned bAddr = (unsigned)__cvta_generic_to_shared(&Bs[(wn * 64 + rB) * PAD + kB]);

    int sr = tid >> 2;
    int kq = (tid & 3) * 4;
    const float* w2e = w2 + (size_t)e * HH * II;
    const float* aptr[4];
    const float* bptr[4];
    unsigned aDst[4];
    #pragma unroll
    for (int i = 0; i < 4; i++) {
        int row = sr + i * 32;
        int s = slots[row];
        aptr[i] = g_s + (size_t)((s >= 0) ? s : 0) * II + kq;
        bptr[i] = w2e + (size_t)(ntB + row) * II + kq;
        aDst[i] = (unsigned)__cvta_generic_to_shared(&As[row * PAD + kq]);
    }

    float acc[4][8][4] = {};
    float4 bv[4];

    #pragma unroll
    for (int i = 0; i < 4; i++) {
        float4 b0 = *(const float4*)(bptr[i]);
        uint4 u;
        u.x = f2tf(b0.x); u.y = f2tf(b0.y); u.z = f2tf(b0.z); u.w = f2tf(b0.w);
        *(uint4*)&Bs[(sr + i * 32) * PAD + kq] = u;
    }
    #pragma unroll
    for (int i = 0; i < 4; i++) cp16(aDst[i], aptr[i]);
    CP_COMMIT();
    #pragma unroll
    for (int i = 0; i < 4; i++) cp16(aDst[i] + STG_WORDS * 4, aptr[i] + BK);
    CP_COMMIT();
    #pragma unroll
    for (int i = 0; i < 4; i++) bv[i] = *(const float4*)(bptr[i] + BK);

    const int NKT = II / BK;
    for (int kb = 0; kb < NKT; kb++) {
        int cur = kb % NSTG;
        CP_WAIT1();
        __syncthreads();
        if (kb + 1 < NKT) {
            int st = (kb + 1) % NSTG;
            #pragma unroll
            for (int i = 0; i < 4; i++) {
                uint4 u;
                u.x = f2tf(bv[i].x); u.y = f2tf(bv[i].y);
                u.z = f2tf(bv[i].z); u.w = f2tf(bv[i].w);
                *(uint4*)&Bs[st * STG_WORDS + (sr + i * 32) * PAD + kq] = u;
            }
        }
        if (kb + 2 < NKT) {
            int st = (kb + 2) % NSTG;
            int ko = (kb + 2) * BK;
            #pragma unroll
            for (int i = 0; i < 4; i++)
                cp16(aDst[i] + (unsigned)(st * STG_WORDS * 4), aptr[i] + ko);
        }
        CP_COMMIT();
        if (kb + 2 < NKT) {
            int ko = (kb + 2) * BK;
            #pragma unroll
            for (int i = 0; i < 4; i++) bv[i] = *(const float4*)(bptr[i] + ko);
        }
        unsigned aOff = aAddr + (unsigned)(cur * STG_WORDS * 4);
        unsigned bOff = bAddr + (unsigned)(cur * STG_WORDS * 4);
        #pragma unroll
        for (int ks = 0; ks < 2; ks++) {
            unsigned afr[4][4], bfr[4][4];
            #pragma unroll
            for (int sm = 0; sm < 4; sm++)
                ldsm4(afr[sm], aOff + (unsigned)((sm * 16 * PAD + ks * 8) * 4));
            #pragma unroll
            for (int p = 0; p < 4; p++)
                ldsm4(bfr[p], bOff + (unsigned)((p * 16 * PAD + ks * 8) * 4));
            #pragma unroll
            for (int sm = 0; sm < 4; sm++)
                #pragma unroll
                for (int sn = 0; sn < 8; sn++)
                    mma_tf32(acc[sm][sn], afr[sm], &bfr[sn >> 1][(sn & 1) * 2]);
        }
    }

    const float* b2e = b2 + e * HH;
    #pragma unroll
    for (int sm = 0; sm < 4; sm++) {
        int rbase = wm * 64 + sm * 16 + grp;
        #pragma unroll
        for (int half = 0; half < 2; half++) {
            int row = rbase + half * 8;
            int slot = slots[row];
            if (slot < 0) continue;
            float rw = g_slot_w[slot];
            float* yrow = g_y + (size_t)slot * HH;
            #pragma unroll
            for (int sn = 0; sn < 8; sn++) {
                int n = ntB + wn * 64 + sn * 8 + 2 * tig;
                #pragma unroll
                for (int cc = 0; cc < 2; cc++)
                    yrow[n + cc] = (acc[sm][sn][half * 2 + cc] + b2e[n + cc]) * rw;
            }
        }
    }
}

// ---------------- kernel 5: out = x + sum_k y[t*4+k]  (vectorized) ------------
__global__ void finalize_kernel(const float* __restrict__ x,
                                float* __restrict__ out) {
    int q = blockIdx.x * 256 + threadIdx.x;          // float4 index
    int t = q >> 8;                                   // 256 float4 per token
    int h4 = q & 255;
    float4 v = *((const float4*)x + q);
    const float4* yb = (const float4*)(g_y + (size_t)t * KTOP * HH) + h4;
    float4 a = yb[0], b = yb[256], c = yb[512], d = yb[768];
    v.x += a.x + b.x + c.x + d.x;
    v.y += a.y + b.y + c.y + d.y;
    v.z += a.z + b.z + c.z + d.z;
    v.w += a.w + b.w + c.w + d.w;
    *((float4*)out + q) = v;
}

// ---------------- launcher -----------------------------------------------------
extern "C" void kernel_launch(void* const* d_in, const int* in_sizes, int n_in,
                              void* d_out, int out_size) {
    const float* x      = (const float*)d_in[0];
    const float* scale  = (const float*)d_in[1];
    const float* gate_w = (const float*)d_in[2];
    const float* gate_b = (const float*)d_in[3];
    const float* w1     = (const float*)d_in[4];
    const float* b1     = (const float*)d_in[5];
    const float* w2     = (const float*)d_in[6];
    const float* b2     = (const float*)d_in[7];
    float* out = (float*)d_out;

    cudaFuncSetAttribute(mlp1_kernel, cudaFuncAttributeMaxDynamicSharedMemorySize, SMEM_BYTES);
    cudaFuncSetAttribute(mlp2_kernel, cudaFuncAttributeMaxDynamicSharedMemorySize, SMEM_BYTES);

    zero_cnt_kernel<<<1, 32>>>();
    norm_gate_kernel<<<TT, 256>>>(x, scale, gate_w, gate_b);

    dim3 g1(II / BN, TT / BM, NE);
    mlp1_kernel<<<g1, 128, SMEM_BYTES>>>(w1, b1);

    dim3 g2(HH / BN, TT / BM, NE);
    mlp2_kernel<<<g2, 128, SMEM_BYTES>>>(w2, b2);

    finalize_kernel<<<(TT * HH) / 1024, 256>>>(x, out);
}

// round 7
// speedup vs baseline: 1.0140x; 1.0140x over previous
#include <cuda_runtime.h>
#include <math.h>

#define TT 2048
#define HH 1024
#define II 1024
#define NE 16
#define KTOP 4
#define EPSF 1e-5f
#define ALPHAF 1.702f
#define LIMITF 7.0f

#define BM 128
#define BN 128
#define BK 16
#define PAD 20                       // 16+4 words/row -> conflict-free LDSM
#define NSTG 3
#define STG_WORDS (128 * PAD)        // words per stage per operand
#define SMEM_BYTES (NSTG * STG_WORDS * 4 * 2)

// ---------------- scratch (static device globals; no allocation) -------------
__device__ __align__(16) float g_t[TT * HH];            // tf32-rounded rmsnorm out
__device__ __align__(16) float g_s[TT * KTOP * II];     // tf32-rounded swiglu out
__device__ __align__(16) float g_y[TT * KTOP * HH];
__device__ float g_slot_w[TT * KTOP];
__device__ int   g_expert_cnt[NE];
__device__ int   g_expert_slots[NE * TT];

// ---------------- helpers ------------------------------------------------------
__device__ __forceinline__ unsigned f2tf(float f) {
    unsigned r;
    asm("cvt.rna.tf32.f32 %0, %1;" : "=r"(r) : "f"(f));
    return r;
}

__device__ __forceinline__ void mma_tf32(float* d, const unsigned* a, const unsigned* b) {
    asm volatile(
        "mma.sync.aligned.m16n8k8.row.col.f32.tf32.tf32.f32 "
        "{%0,%1,%2,%3}, {%4,%5,%6,%7}, {%8,%9}, {%0,%1,%2,%3};"
        : "+f"(d[0]), "+f"(d[1]), "+f"(d[2]), "+f"(d[3])
        : "r"(a[0]), "r"(a[1]), "r"(a[2]), "r"(a[3]), "r"(b[0]), "r"(b[1]));
}

__device__ __forceinline__ void ldsm4(unsigned* r, unsigned addr) {
    asm volatile("ldmatrix.sync.aligned.m8n8.x4.shared.b16 {%0,%1,%2,%3}, [%4];"
        : "=r"(r[0]), "=r"(r[1]), "=r"(r[2]), "=r"(r[3]) : "r"(addr));
}

__device__ __forceinline__ void cp16(unsigned dst, const void* src) {
    asm volatile("cp.async.cg.shared.global [%0], [%1], 16;" :: "r"(dst), "l"(src));
}
#define CP_COMMIT() asm volatile("cp.async.commit_group;")
#define CP_WAIT1()  asm volatile("cp.async.wait_group 1;")

// ---------------- kernel 0 -----------------------------------------------------
__global__ void zero_cnt_kernel() {
    if (threadIdx.x < NE) g_expert_cnt[threadIdx.x] = 0;
}

// ---------------- kernel 1: fused RMSNorm + gate + top4 + routing -------------
// 256 threads, one token per block. Gate logits computed from UNROUNDED t;
// g_t written tf32-RNA rounded for direct cp.async staging in mlp1.
__global__ void norm_gate_kernel(const float* __restrict__ x,
                                 const float* __restrict__ scale,
                                 const float* __restrict__ gate_w,
                                 const float* __restrict__ gate_b) {
    int t = blockIdx.x;
    int tid = threadIdx.x;
    __shared__ float ts[HH];
    __shared__ float gv[NE];
    __shared__ float red[8];

    float4 v = *((const float4*)(x + (size_t)t * HH) + tid);
    float ss = v.x * v.x + v.y * v.y + v.z * v.z + v.w * v.w;
    #pragma unroll
    for (int o = 16; o; o >>= 1) ss += __shfl_xor_sync(0xffffffffu, ss, o);
    if ((tid & 31) == 0) red[tid >> 5] = ss;
    __syncthreads();
    if (tid < 8) {
        float s2 = red[tid];
        #pragma unroll
        for (int o = 4; o; o >>= 1) s2 += __shfl_xor_sync(0xffu, s2, o);
        if (tid == 0) red[0] = s2;
    }
    __syncthreads();
    float rms = rsqrtf(red[0] * (1.0f / HH) + EPSF);
    float4 sc = *((const float4*)scale + tid);
    float4 tv;
    tv.x = v.x * rms * sc.x; tv.y = v.y * rms * sc.y;
    tv.z = v.z * rms * sc.z; tv.w = v.w * rms * sc.w;
    *((float4*)ts + tid) = tv;
    // rounded copy for the GEMM
    uint4 u;
    u.x = f2tf(tv.x); u.y = f2tf(tv.y); u.z = f2tf(tv.z); u.w = f2tf(tv.w);
    *((uint4*)(g_t + (size_t)t * HH) + tid) = u;
    __syncthreads();

    int g = tid >> 4;
    int j = tid & 15;
    const float* wr = gate_w + g * HH;
    float sum = 0.f;
    for (int h = j; h < HH; h += 16) sum += ts[h] * wr[h];
    #pragma unroll
    for (int o = 8; o; o >>= 1) sum += __shfl_xor_sync(0xffffffffu, sum, o);
    if (j == 0) gv[g] = sum + gate_b[g];
    __syncthreads();

    if (tid == 0) {
        float vals[KTOP];
        int   idx[KTOP];
        bool  used[NE];
        #pragma unroll
        for (int e = 0; e < NE; e++) used[e] = false;
        #pragma unroll
        for (int k = 0; k < KTOP; k++) {
            float best = -INFINITY; int bi = 0;
            for (int e = 0; e < NE; e++)
                if (!used[e] && gv[e] > best) { best = gv[e]; bi = e; }
            used[bi] = true; vals[k] = best; idx[k] = bi;
        }
        float m = vals[0];
        float se = 0.f, w[KTOP];
        #pragma unroll
        for (int k = 0; k < KTOP; k++) { w[k] = __expf(vals[k] - m); se += w[k]; }
        float inv = 1.0f / se;
        #pragma unroll
        for (int k = 0; k < KTOP; k++) {
            int slot = t * KTOP + k;
            g_slot_w[slot] = w[k] * inv;
            int pos = atomicAdd(&g_expert_cnt[idx[k]], 1);
            g_expert_slots[idx[k] * TT + pos] = slot;
        }
    }
}

// ================= tf32 GEMMs ====================================================
// 128x128 block, 4 warps (64x64 warp tile), ldmatrix frags.
// A staged by 3-stage cp.async (source pre-rounded); B staged LDG->cvt->STS with
// one-iteration lookahead.

// ---------------- kernel 3: GEMM1 (even w1 rows) + bias + swiglu --------------
__global__ void __launch_bounds__(128, 2) mlp1_kernel(const float* __restrict__ w1,
                                                      const float* __restrict__ b1) {
    int e = blockIdx.z;
    int cnt = g_expert_cnt[e];
    int mt = blockIdx.y;
    if (mt * BM >= cnt) return;
    int ntB = blockIdx.x * BN;

    extern __shared__ __align__(16) unsigned smem[];
    unsigned* As = smem;                       // [NSTG][128][PAD]
    unsigned* Bs = smem + NSTG * STG_WORDS;    // [NSTG][128][PAD]
    __shared__ int slots[BM];

    int tid = threadIdx.x;
    {
        int idx = mt * BM + tid;
        slots[tid] = (idx < cnt) ? g_expert_slots[e * TT + idx] : -1;
    }
    __syncthreads();

    int lane = tid & 31, wid = tid >> 5;
    int wm = wid & 1, wn = wid >> 1;
    int grp = lane >> 2, tig = lane & 3;
    int rA = (lane & 7) + (((lane >> 3) & 1) << 3);
    int kA = (lane >> 4) << 2;
    int rB = (lane & 7) + ((lane >> 4) << 3);
    int kB = ((lane >> 3) & 1) << 2;
    unsigned aAddr = (unsigned)__cvta_generic_to_shared(&As[(wm * 64 + rA) * PAD + kA]);
    unsigned bAddr = (unsigned)__cvta_generic_to_shared(&Bs[(wn * 64 + rB) * PAD + kB]);

    int sr = tid >> 2;
    int kq = (tid & 3) * 4;
    const float* w1e = w1 + (size_t)e * (2 * II) * HH;
    const float* aptr[4];
    const float* bptr[4];
    unsigned aDst[4];
    #pragma unroll
    for (int i = 0; i < 4; i++) {
        int row = sr + i * 32;
        int s = slots[row];
        aptr[i] = g_t + (size_t)((s >= 0) ? (s >> 2) : 0) * HH + kq;
        bptr[i] = w1e + (size_t)(2 * (ntB + row)) * HH + kq;
        aDst[i] = (unsigned)__cvta_generic_to_shared(&As[row * PAD + kq]);
    }

    float acc[4][8][4] = {};
    float4 bv[4];

    // prologue: B stage0 LDG+cvt+STS; A stage0/1 cp.async; B stage1 LDG
    #pragma unroll
    for (int i = 0; i < 4; i++) {
        float4 b0 = *(const float4*)(bptr[i]);
        uint4 u;
        u.x = f2tf(b0.x); u.y = f2tf(b0.y); u.z = f2tf(b0.z); u.w = f2tf(b0.w);
        *(uint4*)&Bs[(sr + i * 32) * PAD + kq] = u;
    }
    #pragma unroll
    for (int i = 0; i < 4; i++) cp16(aDst[i], aptr[i]);
    CP_COMMIT();
    #pragma unroll
    for (int i = 0; i < 4; i++) cp16(aDst[i] + STG_WORDS * 4, aptr[i] + BK);
    CP_COMMIT();
    #pragma unroll
    for (int i = 0; i < 4; i++) bv[i] = *(const float4*)(bptr[i] + BK);

    const int NKT = HH / BK;
    for (int kb = 0; kb < NKT; kb++) {
        int cur = kb % NSTG;
        CP_WAIT1();
        __syncthreads();
        if (kb + 1 < NKT) {                      // STS B stage kb+1
            int st = (kb + 1) % NSTG;
            #pragma unroll
            for (int i = 0; i < 4; i++) {
                uint4 u;
                u.x = f2tf(bv[i].x); u.y = f2tf(bv[i].y);
                u.z = f2tf(bv[i].z); u.w = f2tf(bv[i].w);
                *(uint4*)&Bs[st * STG_WORDS + (sr + i * 32) * PAD + kq] = u;
            }
        }
        if (kb + 2 < NKT) {                      // A cp.async stage kb+2
            int st = (kb + 2) % NSTG;
            int ko = (kb + 2) * BK;
            #pragma unroll
            for (int i = 0; i < 4; i++)
                cp16(aDst[i] + (unsigned)(st * STG_WORDS * 4), aptr[i] + ko);
        }
        CP_COMMIT();
        if (kb + 2 < NKT) {                      // B LDG stage kb+2
            int ko = (kb + 2) * BK;
            #pragma unroll
            for (int i = 0; i < 4; i++) bv[i] = *(const float4*)(bptr[i] + ko);
        }
        unsigned aOff = aAddr + (unsigned)(cur * STG_WORDS * 4);
        unsigned bOff = bAddr + (unsigned)(cur * STG_WORDS * 4);
        #pragma unroll
        for (int ks = 0; ks < 2; ks++) {
            unsigned afr[4][4], bfr[4][4];
            #pragma unroll
            for (int sm = 0; sm < 4; sm++)
                ldsm4(afr[sm], aOff + (unsigned)((sm * 16 * PAD + ks * 8) * 4));
            #pragma unroll
            for (int p = 0; p < 4; p++)
                ldsm4(bfr[p], bOff + (unsigned)((p * 16 * PAD + ks * 8) * 4));
            #pragma unroll
            for (int sm = 0; sm < 4; sm++)
                #pragma unroll
                for (int sn = 0; sn < 8; sn++)
                    mma_tf32(acc[sm][sn], afr[sm], &bfr[sn >> 1][(sn & 1) * 2]);
        }
    }

    const float* b1e = b1 + e * (2 * II);
    #pragma unroll
    for (int sm = 0; sm < 4; sm++) {
        int rbase = wm * 64 + sm * 16 + grp;
        #pragma unroll
        for (int half = 0; half < 2; half++) {
            int row = rbase + half * 8;
            int slot = slots[row];
            if (slot < 0) continue;
            float* srow = g_s + (size_t)slot * II;
            #pragma unroll
            for (int sn = 0; sn < 8; sn++) {
                int n = ntB + wn * 64 + sn * 8 + 2 * tig;
                #pragma unroll
                for (int cc = 0; cc < 2; cc++) {
                    float hsum = acc[sm][sn][half * 2 + cc] + b1e[2 * (n + cc)];
                    float gl = fminf(hsum, LIMITF);
                    float sig = 1.0f / (1.0f + __expf(-ALPHAF * gl));
                    // store tf32-rounded so mlp2 can cp.async it directly
                    srow[n + cc] = __uint_as_float(f2tf(gl * sig * (LIMITF + 1.0f)));
                }
            }
        }
    }
}

// ---------------- kernel 4: GEMM2 + bias, scaled by routing weight ------------
__global__ void __launch_bounds__(128, 2) mlp2_kernel(const float* __restrict__ w2,
                                                      const float* __restrict__ b2) {
    int e = blockIdx.z;
    int cnt = g_expert_cnt[e];
    int mt = blockIdx.y;
    if (mt * BM >= cnt) return;
    int ntB = blockIdx.x * BN;

    extern __shared__ __align__(16) unsigned smem[];
    unsigned* As = smem;
    unsigned* Bs = smem + NSTG * STG_WORDS;
    __shared__ int slots[BM];

    int tid = threadIdx.x;
    {
        int idx = mt * BM + tid;
        slots[tid] = (idx < cnt) ? g_expert_slots[e * TT + idx] : -1;
    }
    __syncthreads();

    int lane = tid & 31, wid = tid >> 5;
    int wm = wid & 1, wn = wid >> 1;
    int grp = lane >> 2, tig = lane & 3;
    int rA = (lane & 7) + (((lane >> 3) & 1) << 3);
    int kA = (lane >> 4) << 2;
    int rB = (lane & 7) + ((lane >> 4) << 3);
    int kB = ((lane >> 3) & 1) << 2;
    unsigned aAddr = (unsigned)__cvta_generic_to_shared(&As[(wm * 64 + rA) * PAD + kA]);
    unsigned bAddr = (unsigned)__cvta_generic_to_shared(&Bs[(wn * 64 + rB) * PAD + kB]);

    int sr = tid >> 2;
    int kq = (tid & 3) * 4;
    const float* w2e = w2 + (size_t)e * HH * II;
    const float* aptr[4];
    const float* bptr[4];
    unsigned aDst[4];
    #pragma unroll
    for (int i = 0; i < 4; i++) {
        int row = sr + i * 32;
        int s = slots[row];
        aptr[i] = g_s + (size_t)((s >= 0) ? s : 0) * II + kq;
        bptr[i] = w2e + (size_t)(ntB + row) * II + kq;
        aDst[i] = (unsigned)__cvta_generic_to_shared(&As[row * PAD + kq]);
    }

    float acc[4][8][4] = {};
    float4 bv[4];

    #pragma unroll
    for (int i = 0; i < 4; i++) {
        float4 b0 = *(const float4*)(bptr[i]);
        uint4 u;
        u.x = f2tf(b0.x); u.y = f2tf(b0.y); u.z = f2tf(b0.z); u.w = f2tf(b0.w);
        *(uint4*)&Bs[(sr + i * 32) * PAD + kq] = u;
    }
    #pragma unroll
    for (int i = 0; i < 4; i++) cp16(aDst[i], aptr[i]);
    CP_COMMIT();
    #pragma unroll
    for (int i = 0; i < 4; i++) cp16(aDst[i] + STG_WORDS * 4, aptr[i] + BK);
    CP_COMMIT();
    #pragma unroll
    for (int i = 0; i < 4; i++) bv[i] = *(const float4*)(bptr[i] + BK);

    const int NKT = II / BK;
    for (int kb = 0; kb < NKT; kb++) {
        int cur = kb % NSTG;
        CP_WAIT1();
        __syncthreads();
        if (kb + 1 < NKT) {
            int st = (kb + 1) % NSTG;
            #pragma unroll
            for (int i = 0; i < 4; i++) {
                uint4 u;
                u.x = f2tf(bv[i].x); u.y = f2tf(bv[i].y);
                u.z = f2tf(bv[i].z); u.w = f2tf(bv[i].w);
                *(uint4*)&Bs[st * STG_WORDS + (sr + i * 32) * PAD + kq] = u;
            }
        }
        if (kb + 2 < NKT) {
            int st = (kb + 2) % NSTG;
            int ko = (kb + 2) * BK;
            #pragma unroll
            for (int i = 0; i < 4; i++)
                cp16(aDst[i] + (unsigned)(st * STG_WORDS * 4), aptr[i] + ko);
        }
        CP_COMMIT();
        if (kb + 2 < NKT) {
            int ko = (kb + 2) * BK;
            #pragma unroll
            for (int i = 0; i < 4; i++) bv[i] = *(const float4*)(bptr[i] + ko);
        }
        unsigned aOff = aAddr + (unsigned)(cur * STG_WORDS * 4);
        unsigned bOff = bAddr + (unsigned)(cur * STG_WORDS * 4);
        #pragma unroll
        for (int ks = 0; ks < 2; ks++) {
            unsigned afr[4][4], bfr[4][4];
            #pragma unroll
            for (int sm = 0; sm < 4; sm++)
                ldsm4(afr[sm], aOff + (unsigned)((sm * 16 * PAD + ks * 8) * 4));
            #pragma unroll
            for (int p = 0; p < 4; p++)
                ldsm4(bfr[p], bOff + (unsigned)((p * 16 * PAD + ks * 8) * 4));
            #pragma unroll
            for (int sm = 0; sm < 4; sm++)
                #pragma unroll
                for (int sn = 0; sn < 8; sn++)
                    mma_tf32(acc[sm][sn], afr[sm], &bfr[sn >> 1][(sn & 1) * 2]);
        }
    }

    const float* b2e = b2 + e * HH;
    #pragma unroll
    for (int sm = 0; sm < 4; sm++) {
        int rbase = wm * 64 + sm * 16 + grp;
        #pragma unroll
        for (int half = 0; half < 2; half++) {
            int row = rbase + half * 8;
            int slot = slots[row];
            if (slot < 0) continue;
            float rw = g_slot_w[slot];
            float* yrow = g_y + (size_t)slot * HH;
            #pragma unroll
            for (int sn = 0; sn < 8; sn++) {
                int n = ntB + wn * 64 + sn * 8 + 2 * tig;
                #pragma unroll
                for (int cc = 0; cc < 2; cc++)
                    yrow[n + cc] = (acc[sm][sn][half * 2 + cc] + b2e[n + cc]) * rw;
            }
        }
    }
}

// ---------------- kernel 5: out = x + sum_k y[t*4+k]  (vectorized) ------------
__global__ void finalize_kernel(const float* __restrict__ x,
                                float* __restrict__ out) {
    int q = blockIdx.x * 256 + threadIdx.x;          // float4 index
    int t = q >> 8;                                   // 256 float4 per token
    int h4 = q & 255;
    float4 v = *((const float4*)x + q);
    const float4* yb = (const float4*)(g_y + (size_t)t * KTOP * HH) + h4;
    float4 a = yb[0], b = yb[256], c = yb[512], d = yb[768];
    v.x += a.x + b.x + c.x + d.x;
    v.y += a.y + b.y + c.y + d.y;
    v.z += a.z + b.z + c.z + d.z;
    v.w += a.w + b.w + c.w + d.w;
    *((float4*)out + q) = v;
}

// ---------------- launcher -----------------------------------------------------
extern "C" void kernel_launch(void* const* d_in, const int* in_sizes, int n_in,
                              void* d_out, int out_size) {
    const float* x      = (const float*)d_in[0];
    const float* scale  = (const float*)d_in[1];
    const float* gate_w = (const float*)d_in[2];
    const float* gate_b = (const float*)d_in[3];
    const float* w1     = (const float*)d_in[4];
    const float* b1     = (const float*)d_in[5];
    const float* w2     = (const float*)d_in[6];
    const float* b2     = (const float*)d_in[7];
    float* out = (float*)d_out;

    cudaFuncSetAttribute(mlp1_kernel, cudaFuncAttributeMaxDynamicSharedMemorySize, SMEM_BYTES);
    cudaFuncSetAttribute(mlp2_kernel, cudaFuncAttributeMaxDynamicSharedMemorySize, SMEM_BYTES);

    zero_cnt_kernel<<<1, 32>>>();
    norm_gate_kernel<<<TT, 256>>>(x, scale, gate_w, gate_b);

    dim3 g1(II / BN, TT / BM, NE);
    mlp1_kernel<<<g1, 128, SMEM_BYTES>>>(w1, b1);

    dim3 g2(HH / BN, TT / BM, NE);
    mlp2_kernel<<<g2, 128, SMEM_BYTES>>>(w2, b2);

    finalize_kernel<<<(TT * HH) / 1024, 256>>>(x, out);
}